// round 13
// baseline (speedup 1.0000x reference)
#include <cuda_runtime.h>
#include <cuda_fp16.h>
#include <math.h>
#include <stdint.h>

// ---------------- problem constants ----------------
#define cN 10000
#define cE 40000
#define cD 64
#define cB 512
#define cFIN 11
#define cEF 5
#define cH 128
#define cDSQ 4096

// ---------------- device scratch ----------------
__device__ float g_h0[cN * cD];
__device__ float g_h1[cN * cD];
__device__ __half g_hreluh[cE * cH];          // 10 MB fp16 edge-net hidden
__device__ __half g_w2T[cDSQ * cH];           // 1 MB fp16 transposed [n][k]
__device__ __half g_ewh[(size_t)cE * cDSQ];   // 320 MB fp16 edge weights (bias folded in)
__device__ float g_agg[cN * cD];
__device__ float g_CG[cN * 4 * cD];           // [N,256] = [croot | G2]
__device__ float g_G1[cN * 3 * cD];
__device__ float g_Wcat[cD * 4 * cD];         // [64,256] = [conv_root | gru_w_hh]
__device__ float g_bcat[4 * cD];
__device__ float g_deg[cN];

// ---------------- helpers ----------------
__device__ __forceinline__ float sigm(float x) { return 1.0f / (1.0f + expf(-x)); }

__device__ __forceinline__ uint32_t f2tf32(float f) {
    uint32_t u;
    asm("cvt.rna.tf32.f32 %0, %1;" : "=r"(u) : "f"(f));
    return u;
}
__device__ __forceinline__ void mma_tf32(float* d, const uint32_t* a, const uint32_t* b) {
    asm volatile(
        "mma.sync.aligned.m16n8k8.row.col.f32.tf32.tf32.f32 "
        "{%0,%1,%2,%3}, {%4,%5,%6,%7}, {%8,%9}, {%0,%1,%2,%3};"
        : "+f"(d[0]), "+f"(d[1]), "+f"(d[2]), "+f"(d[3])
        : "r"(a[0]), "r"(a[1]), "r"(a[2]), "r"(a[3]), "r"(b[0]), "r"(b[1]));
}
__device__ __forceinline__ void mma_f16(float* d, const uint32_t* a, const uint32_t* b) {
    asm volatile(
        "mma.sync.aligned.m16n8k16.row.col.f32.f16.f16.f32 "
        "{%0,%1,%2,%3}, {%4,%5,%6,%7}, {%8,%9}, {%0,%1,%2,%3};"
        : "+f"(d[0]), "+f"(d[1]), "+f"(d[2]), "+f"(d[3])
        : "r"(a[0]), "r"(a[1]), "r"(a[2]), "r"(a[3]), "r"(b[0]), "r"(b[1]));
}
__device__ __forceinline__ void cp16(void* smem, const void* gmem) {
    uint32_t s = (uint32_t)__cvta_generic_to_shared(smem);
    asm volatile("cp.async.ca.shared.global [%0], [%1], 16;" :: "r"(s), "l"(gmem));
}
__device__ __forceinline__ void stcs_h2(__half2* addr, __half2 v) {
    uint32_t b = *(uint32_t*)&v;
    asm volatile("st.global.cs.b32 [%0], %1;" :: "l"(addr), "r"(b) : "memory");
}

// ---------------- small kernels ----------------
__global__ void k_deg_zero(float* deg) {
    int i = blockIdx.x * blockDim.x + threadIdx.x;
    if (i < cN) deg[i] = 0.0f;
}
__global__ void k_deg(const int* __restrict__ dst, float* deg) {
    int e = blockIdx.x * blockDim.x + threadIdx.x;
    if (e < cE) atomicAdd(&deg[dst[e]], 1.0f);
}
// lin0 -> h0; also zero agg for step 0
__global__ void k_lin0(const float* __restrict__ x, const float* __restrict__ w,
                       const float* __restrict__ b, float* __restrict__ h0,
                       float* __restrict__ agg) {
    int idx = blockIdx.x * blockDim.x + threadIdx.x;
    if (idx >= cN * cD) return;
    int n = idx >> 6, d = idx & 63;
    float acc = b[d];
    const float* xr = x + n * cFIN;
#pragma unroll
    for (int i = 0; i < cFIN; i++) acc += xr[i] * w[i * cD + d];
    h0[idx] = fmaxf(acc, 0.0f);
    agg[idx] = 0.0f;
}
// edge-net layer 1, fp16 output, 2 outputs per thread
__global__ void k_edge1(const float* __restrict__ ea, const float* __restrict__ w1,
                        const float* __restrict__ b1, __half* __restrict__ hrelu) {
    int idx = blockIdx.x * blockDim.x + threadIdx.x;
    if (idx >= cE * (cH / 2)) return;
    int e = idx >> 6, j2 = (idx & 63) * 2;
    float acc0 = b1[j2], acc1 = b1[j2 + 1];
    const float* er = ea + e * cEF;
#pragma unroll
    for (int i = 0; i < cEF; i++) {
        float ev = er[i];
        float2 wp = *(const float2*)(w1 + i * cH + j2);
        acc0 += ev * wp.x;
        acc1 += ev * wp.y;
    }
    *(__half2*)(hrelu + (size_t)e * cH + j2) =
        __floats2half2_rn(fmaxf(acc0, 0.0f), fmaxf(acc1, 0.0f));
}
// w2T[n][k] = half(w2[k][n])
__global__ void k_prepB(const float* __restrict__ w2, __half* __restrict__ BT) {
    int idx = blockIdx.x * blockDim.x + threadIdx.x;
    if (idx >= cH * cDSQ) return;
    int n = idx >> 7, k = idx & 127;
    BT[idx] = __float2half(w2[(size_t)k * cDSQ + n]);
}
// Wcat [64][256] = [conv_root | gru_w_hh]; bcat [256] = [0 | gru_b_hh]
__global__ void k_prepW(const float* __restrict__ wroot, const float* __restrict__ whh,
                        const float* __restrict__ bhh,
                        float* __restrict__ Wcat, float* __restrict__ bcat) {
    int idx = blockIdx.x * blockDim.x + threadIdx.x;
    if (idx < cD * 4 * cD) {
        int k = idx >> 8, col = idx & 255;
        Wcat[idx] = (col < cD) ? wroot[k * cD + col] : whh[k * 3 * cD + (col - cD)];
    }
    if (idx < 4 * cD) bcat[idx] = (idx < cD) ? 0.0f : bhh[idx - cD];
}

// -------- fp16 tensor GEMM for ew: half C[E,4096] = A[E,128] @ B[128,4096] + bias --------
// CTA tile 128m x 64n, full K=128 resident, 8 warps (4x2), warp tile 32x32.
// ~60-70 regs/thread + 52 KB smem -> 4 CTAs/SM for load/MMA/store overlap.
#define EW_SMEM (128 * 136 * 2 + 64 * 136 * 2)
__global__ void __launch_bounds__(256) k_ewgemm(const __half* __restrict__ Ah,
                                                const __half* __restrict__ BTh,
                                                const float* __restrict__ bias,
                                                __half* __restrict__ C) {
    extern __shared__ __half ew_sm[];
    __half* As_h = ew_sm;                 // [128][136]
    __half* Bs_h = ew_sm + 128 * 136;     // [64][136]

    const int tid = threadIdx.x;
    const int warp = tid >> 5, lane = tid & 31;
    const int wm = warp >> 1, wn = warp & 1;   // 4 x 2 warp grid
    const int g = lane >> 2, c = lane & 3;
    const int rowBase = blockIdx.y * 128;
    const int colBase = blockIdx.x * 64;

    // load A tile: 128 rows x 128 halves (16B chunks)
#pragma unroll
    for (int it = 0; it < 8; it++) {
        int idx = tid + it * 256;
        int row = idx >> 4, q = idx & 15;
        int grow = rowBase + row;
        __half* dstp = As_h + row * 136 + q * 8;
        if (grow < cE) cp16(dstp, Ah + (size_t)grow * cH + q * 8);
        else *(uint4*)dstp = make_uint4(0u, 0u, 0u, 0u);
    }
    // load B tile: 64 n-rows x 128 halves
#pragma unroll
    for (int it = 0; it < 4; it++) {
        int idx = tid + it * 256;
        int n = idx >> 4, q = idx & 15;
        cp16(Bs_h + n * 136 + q * 8, BTh + (size_t)(colBase + n) * cH + q * 8);
    }
    asm volatile("cp.async.commit_group;");
    asm volatile("cp.async.wait_group 0;");
    __syncthreads();

    float acc[2][4][4];
#pragma unroll
    for (int mt = 0; mt < 2; mt++)
#pragma unroll
        for (int nt = 0; nt < 4; nt++)
#pragma unroll
            for (int j = 0; j < 4; j++) acc[mt][nt][j] = 0.0f;

#pragma unroll
    for (int ks = 0; ks < 8; ks++) {
        const int k0 = ks * 16;
        uint32_t af[2][4];
#pragma unroll
        for (int mt = 0; mt < 2; mt++) {
            int r = wm * 32 + mt * 16 + g;
            af[mt][0] = *(const uint32_t*)&As_h[r * 136 + k0 + 2 * c];
            af[mt][1] = *(const uint32_t*)&As_h[(r + 8) * 136 + k0 + 2 * c];
            af[mt][2] = *(const uint32_t*)&As_h[r * 136 + k0 + 2 * c + 8];
            af[mt][3] = *(const uint32_t*)&As_h[(r + 8) * 136 + k0 + 2 * c + 8];
        }
#pragma unroll
        for (int nt = 0; nt < 4; nt++) {
            int n = wn * 32 + nt * 8 + g;
            uint32_t bf[2];
            bf[0] = *(const uint32_t*)&Bs_h[n * 136 + k0 + 2 * c];
            bf[1] = *(const uint32_t*)&Bs_h[n * 136 + k0 + 2 * c + 8];
            mma_f16(acc[0][nt], af[0], bf);
            mma_f16(acc[1][nt], af[1], bf);
        }
    }

#pragma unroll
    for (int mt = 0; mt < 2; mt++) {
        int r0 = rowBase + wm * 32 + mt * 16 + g;
#pragma unroll
        for (int nt = 0; nt < 4; nt++) {
            int cc = colBase + wn * 32 + nt * 8 + c * 2;
            float b0 = bias[cc], b1 = bias[cc + 1];
            if (r0 < cE)
                stcs_h2((__half2*)(C + (size_t)r0 * cDSQ + cc),
                        __floats2half2_rn(acc[mt][nt][0] + b0, acc[mt][nt][1] + b1));
            if (r0 + 8 < cE)
                stcs_h2((__half2*)(C + (size_t)(r0 + 8) * cDSQ + cc),
                        __floats2half2_rn(acc[mt][nt][2] + b0, acc[mt][nt][3] + b1));
        }
    }
}

// -------- TF32 node GEMM core --------
#define NG_SMEM (64 * 132 * 4 + 64 * 68 * 4)

__device__ __forceinline__ void nodegemm_core(
    uint32_t (*As)[132], uint32_t (*Bs)[68],
    int M, int ldb, const float* __restrict__ Bw,
    const float* __restrict__ bias, float* __restrict__ Cp, int ldc,
    int rowBase, int colBase)
{
    const int tid = threadIdx.x;
    const int warp = tid >> 5, lane = tid & 31;
    const int g = lane >> 2, c = lane & 3;

    {
        int kr = tid >> 1, half = tid & 1;
        const float4* br = (const float4*)(Bw + (size_t)kr * ldb + colBase + half * 32);
#pragma unroll
        for (int q = 0; q < 8; q++) {
            float4 v = br[q];
            int nq = half * 8 + q;
            uint4 u;
            u.x = f2tf32(v.x); u.y = f2tf32(v.y); u.z = f2tf32(v.z); u.w = f2tf32(v.w);
            *(uint4*)&Bs[kr][nq * 4] = u;
        }
    }
    __syncthreads();

    float acc[2][8][4];
#pragma unroll
    for (int mt = 0; mt < 2; mt++)
#pragma unroll
        for (int nt = 0; nt < 8; nt++)
#pragma unroll
            for (int j = 0; j < 4; j++) acc[mt][nt][j] = 0.0f;

    const int r0 = warp * 32;
#pragma unroll
    for (int k0 = 0; k0 < 64; k0 += 8) {
        uint32_t af[2][4];
#pragma unroll
        for (int mt = 0; mt < 2; mt++) {
            int r = r0 + mt * 16 + g;
            af[mt][0] = As[k0 + c][r];
            af[mt][1] = As[k0 + c][r + 8];
            af[mt][2] = As[k0 + c + 4][r];
            af[mt][3] = As[k0 + c + 4][r + 8];
        }
#pragma unroll
        for (int nt = 0; nt < 8; nt++) {
            uint32_t bf[2];
            bf[0] = Bs[k0 + c][nt * 8 + g];
            bf[1] = Bs[k0 + c + 4][nt * 8 + g];
            mma_tf32(acc[0][nt], af[0], bf);
            mma_tf32(acc[1][nt], af[1], bf);
        }
    }

#pragma unroll
    for (int mt = 0; mt < 2; mt++) {
        int rr0 = rowBase + r0 + mt * 16 + g;
        int rr1 = rr0 + 8;
#pragma unroll
        for (int nt = 0; nt < 8; nt++) {
            int cc = colBase + nt * 8 + c * 2;
            float b0 = bias ? bias[cc] : 0.0f;
            float b1 = bias ? bias[cc + 1] : 0.0f;
            if (rr0 < M) {
                float2 v = make_float2(acc[mt][nt][0] + b0, acc[mt][nt][1] + b1);
                *(float2*)(Cp + (size_t)rr0 * ldc + cc) = v;
            }
            if (rr1 < M) {
                float2 v = make_float2(acc[mt][nt][2] + b0, acc[mt][nt][3] + b1);
                *(float2*)(Cp + (size_t)rr1 * ldc + cc) = v;
            }
        }
    }
}

__global__ void __launch_bounds__(128) k_nodegemm(int M, int ldb,
                                                  const float* __restrict__ A,
                                                  const float* __restrict__ Bw,
                                                  const float* __restrict__ bias,
                                                  float* __restrict__ Cp, int ldc) {
    extern __shared__ uint32_t ng_sm[];
    uint32_t (*As)[132] = (uint32_t (*)[132])ng_sm;
    uint32_t (*Bs)[68]  = (uint32_t (*)[68])(ng_sm + 64 * 132);
    const int tid = threadIdx.x;
    const int rowBase = blockIdx.y * 128;
    {
        int grow = rowBase + tid;
        if (grow < M) {
            const float4* ar = (const float4*)(A + (size_t)grow * cD);
#pragma unroll
            for (int q = 0; q < 16; q++) {
                float4 v = ar[q];
                As[q * 4 + 0][tid] = f2tf32(v.x);
                As[q * 4 + 1][tid] = f2tf32(v.y);
                As[q * 4 + 2][tid] = f2tf32(v.z);
                As[q * 4 + 3][tid] = f2tf32(v.w);
            }
        } else {
#pragma unroll
            for (int q = 0; q < 64; q++) As[q][tid] = 0u;
        }
    }
    nodegemm_core(As, Bs, M, ldb, Bw, bias, Cp, ldc, rowBase, blockIdx.x * 64);
}

__global__ void __launch_bounds__(128) k_mgemm(int M, int ldb,
                                               const float* __restrict__ agg,
                                               const float* __restrict__ CG,
                                               const float* __restrict__ deg,
                                               const float* __restrict__ cbias,
                                               const float* __restrict__ Bw,
                                               const float* __restrict__ bias,
                                               float* __restrict__ Cp, int ldc) {
    extern __shared__ uint32_t ng_sm[];
    uint32_t (*As)[132] = (uint32_t (*)[132])ng_sm;
    uint32_t (*Bs)[68]  = (uint32_t (*)[68])(ng_sm + 64 * 132);
    const int tid = threadIdx.x;
    const int rowBase = blockIdx.y * 128;
    {
        int grow = rowBase + tid;
        if (grow < M) {
            float inv = 1.0f / fmaxf(deg[grow], 1.0f);
            const float4* ag = (const float4*)(agg + (size_t)grow * cD);
            const float4* cg = (const float4*)(CG + (size_t)grow * 4 * cD);
            const float4* cb = (const float4*)(cbias);
#pragma unroll
            for (int q = 0; q < 16; q++) {
                float4 a = ag[q], cr = cg[q], bb = cb[q];
                As[q * 4 + 0][tid] = f2tf32(fmaxf(a.x * inv + cr.x + bb.x, 0.0f));
                As[q * 4 + 1][tid] = f2tf32(fmaxf(a.y * inv + cr.y + bb.y, 0.0f));
                As[q * 4 + 2][tid] = f2tf32(fmaxf(a.z * inv + cr.z + bb.z, 0.0f));
                As[q * 4 + 3][tid] = f2tf32(fmaxf(a.w * inv + cr.w + bb.w, 0.0f));
            }
        } else {
#pragma unroll
            for (int q = 0; q < 64; q++) As[q][tid] = 0u;
        }
    }
    nodegemm_core(As, Bs, M, ldb, Bw, bias, Cp, ldc, rowBase, blockIdx.x * 64);
}

// -------- per-edge matvec + scatter: 2 warps per edge (row-split), streaming loads --------
__global__ void k_msg(const float* __restrict__ out, const __half* __restrict__ ew,
                      const int* __restrict__ src, const int* __restrict__ dst,
                      float* __restrict__ agg) {
    int w = blockIdx.x * blockDim.y + threadIdx.y;   // global warp id
    int e = w >> 1;
    if (e >= cE) return;
    int half = w & 1;                                 // row half: 0 -> rows 0..31, 1 -> 32..63
    int lane = threadIdx.x;
    int s = src[e];
    float v = __ldg(out + (size_t)s * cD + half * 32 + lane);
    const uint4* wp = (const uint4*)(ew + (size_t)e * cDSQ);
    const int rl = lane >> 3, cl8 = lane & 7;
    const int rbase = half * 32;
    float acc[8];
#pragma unroll
    for (int q = 0; q < 8; q++) acc[q] = 0.0f;

#pragma unroll
    for (int j = 0; j < 8; j++) {
        int rloc = j * 4 + rl;
        float vv = __shfl_sync(0xffffffffu, v, rloc);
        uint4 u = __ldcs(&wp[(rbase + rloc) * 8 + cl8]);
        __half2* h2 = (__half2*)&u;
#pragma unroll
        for (int q = 0; q < 4; q++) {
            float2 f = __half22float2(h2[q]);
            acc[q * 2]     += vv * f.x;
            acc[q * 2 + 1] += vv * f.y;
        }
    }
#pragma unroll
    for (int off = 8; off <= 16; off <<= 1)
#pragma unroll
        for (int q = 0; q < 8; q++)
            acc[q] += __shfl_xor_sync(0xffffffffu, acc[q], off);

    int dn = dst[e];
    int col = cl8 * 8 + rl * 2;
    atomicAdd(&agg[(size_t)dn * cD + col],     acc[rl * 2]);
    atomicAdd(&agg[(size_t)dn * cD + col + 1], acc[rl * 2 + 1]);
}

// GRU gates; also zeroes agg for the next step
__global__ void k_gate(const float* __restrict__ G1, const float* __restrict__ CG,
                       const float* __restrict__ h, float* __restrict__ hn,
                       float* __restrict__ agg) {
    int idx = blockIdx.x * blockDim.x + threadIdx.x;
    if (idx >= cN * cD) return;
    int n = idx >> 6, d = idx & 63;
    const float* g1 = G1 + (size_t)n * 3 * cD;
    const float* g2 = CG + (size_t)n * 4 * cD + cD;
    float r = sigm(g1[d] + g2[d]);
    float z = sigm(g1[cD + d] + g2[cD + d]);
    float nn = tanhf(g1[2 * cD + d] + r * g2[2 * cD + d]);
    hn[idx] = (1.0f - z) * nn + z * h[idx];
    agg[idx] = 0.0f;
}

// -------- fused Set2Set (3 iterations) + final lin1 --------
__global__ void __launch_bounds__(128) k_set2set(
    const float* __restrict__ hfin, const int* __restrict__ batch,
    const float* __restrict__ w_ih, const float* __restrict__ w_hh,
    const float* __restrict__ b_ih, const float* __restrict__ b_hh,
    const float* __restrict__ l1w, const float* __restrict__ l1b,
    float* __restrict__ outp)
{
    const int b = blockIdx.x;
    const int tid = threadIdx.x, warp = tid >> 5, lane = tid & 31;
    __shared__ float s_qstar[128], s_g[256], s_q[64], s_cl[64], s_rvec[64];
    __shared__ float s_wmax[4], s_wsum[4];
    __shared__ float s_gmax, s_gsum;
    __shared__ int s_s, s_e;

    if (tid == 0) {
        int lo = 0, hi = cN;
        while (lo < hi) { int mid = (lo + hi) >> 1; if (batch[mid] < b) lo = mid + 1; else hi = mid; }
        s_s = lo;
        hi = cN;
        while (lo < hi) { int mid = (lo + hi) >> 1; if (batch[mid] < b + 1) lo = mid + 1; else hi = mid; }
        s_e = lo;
    }
    s_qstar[tid] = 0.0f;
    if (tid < 64) { s_q[tid] = 0.0f; s_cl[tid] = 0.0f; }
    __syncthreads();

    for (int t = 0; t < 3; t++) {
        float g0 = b_ih[tid] + b_hh[tid];
        float g1 = b_ih[tid + 128] + b_hh[tid + 128];
#pragma unroll 4
        for (int k = 0; k < 128; k++) {
            float qv = s_qstar[k];
            g0 += qv * w_ih[k * 256 + tid];
            g1 += qv * w_ih[k * 256 + tid + 128];
        }
#pragma unroll 4
        for (int k = 0; k < 64; k++) {
            float hv = s_q[k];
            g0 += hv * w_hh[k * 256 + tid];
            g1 += hv * w_hh[k * 256 + tid + 128];
        }
        s_g[tid] = g0; s_g[tid + 128] = g1;
        __syncthreads();
        if (tid < 64) {
            float ig = sigm(s_g[tid]), fg = sigm(s_g[64 + tid]);
            float gg = tanhf(s_g[128 + tid]), og = sigm(s_g[192 + tid]);
            float c = fg * s_cl[tid] + ig * gg;
            s_cl[tid] = c;
            s_q[tid] = og * tanhf(c);
            s_rvec[tid] = 0.0f;
        }
        __syncthreads();

        const int ns = s_s, ne = s_e;
        float wmax = -1e30f;
        for (int n = ns + warp; n < ne; n += 4) {
            const float* o = hfin + (size_t)n * cD;
            float d = o[lane] * s_q[lane] + o[32 + lane] * s_q[32 + lane];
#pragma unroll
            for (int off = 16; off; off >>= 1) d += __shfl_xor_sync(0xffffffffu, d, off);
            wmax = fmaxf(wmax, d);
        }
        if (lane == 0) s_wmax[warp] = wmax;
        __syncthreads();
        if (tid == 0)
            s_gmax = fmaxf(fmaxf(s_wmax[0], s_wmax[1]), fmaxf(s_wmax[2], s_wmax[3]));
        __syncthreads();
        const float gmax = s_gmax;

        float wsum = 0.0f, rv0 = 0.0f, rv1 = 0.0f;
        for (int n = ns + warp; n < ne; n += 4) {
            const float* o = hfin + (size_t)n * cD;
            float d = o[lane] * s_q[lane] + o[32 + lane] * s_q[32 + lane];
#pragma unroll
            for (int off = 16; off; off >>= 1) d += __shfl_xor_sync(0xffffffffu, d, off);
            float ee = expf(d - gmax);
            wsum += ee;
            rv0 += ee * o[lane];
            rv1 += ee * o[32 + lane];
        }
        if (lane == 0) s_wsum[warp] = wsum;
        atomicAdd(&s_rvec[lane], rv0);
        atomicAdd(&s_rvec[32 + lane], rv1);
        __syncthreads();
        if (tid == 0) s_gsum = s_wsum[0] + s_wsum[1] + s_wsum[2] + s_wsum[3];
        __syncthreads();

        if (tid < 64) s_qstar[tid] = s_q[tid];
        else {
            float denom = s_gsum;
            s_qstar[tid] = (denom > 0.0f) ? s_rvec[tid - 64] / denom : 0.0f;
        }
        __syncthreads();
    }

    if (tid < 64) {
        float acc = l1b[tid];
#pragma unroll 4
        for (int k = 0; k < 128; k++) acc += s_qstar[k] * l1w[k * cD + tid];
        outp[b * cD + tid] = fmaxf(acc, 0.0f);
    }
}

// ---------------- launch ----------------
extern "C" void kernel_launch(void* const* d_in, const int* in_sizes, int n_in,
                              void* d_out, int out_size) {
    const float* x        = (const float*)d_in[0];
    const float* ea       = (const float*)d_in[1];
    const int*   ei       = (const int*)d_in[2];
    const int*   batch    = (const int*)d_in[3];
    const float* lin0_w   = (const float*)d_in[4];
    const float* lin0_b   = (const float*)d_in[5];
    const float* net_w1   = (const float*)d_in[6];
    const float* net_b1   = (const float*)d_in[7];
    const float* net_w2   = (const float*)d_in[8];
    const float* net_b2   = (const float*)d_in[9];
    const float* conv_root= (const float*)d_in[10];
    const float* conv_bias= (const float*)d_in[11];
    const float* gru_w_ih = (const float*)d_in[12];
    const float* gru_w_hh = (const float*)d_in[13];
    const float* gru_b_ih = (const float*)d_in[14];
    const float* gru_b_hh = (const float*)d_in[15];
    const float* lstm_w_ih= (const float*)d_in[16];
    const float* lstm_w_hh= (const float*)d_in[17];
    const float* lstm_b_ih= (const float*)d_in[18];
    const float* lstm_b_hh= (const float*)d_in[19];
    const float* lin1_w   = (const float*)d_in[20];
    const float* lin1_b   = (const float*)d_in[21];
    float* out = (float*)d_out;

    const int* src = ei;
    const int* dst = ei + cE;

    void* p;
    cudaGetSymbolAddress(&p, g_h0);     float* p_h0 = (float*)p;
    cudaGetSymbolAddress(&p, g_h1);     float* p_h1 = (float*)p;
    cudaGetSymbolAddress(&p, g_hreluh); __half* p_hrh = (__half*)p;
    cudaGetSymbolAddress(&p, g_w2T);    __half* p_w2T = (__half*)p;
    cudaGetSymbolAddress(&p, g_ewh);    __half* p_ewh = (__half*)p;
    cudaGetSymbolAddress(&p, g_agg);    float* p_agg = (float*)p;
    cudaGetSymbolAddress(&p, g_CG);     float* p_CG = (float*)p;
    cudaGetSymbolAddress(&p, g_G1);     float* p_G1 = (float*)p;
    cudaGetSymbolAddress(&p, g_Wcat);   float* p_Wcat = (float*)p;
    cudaGetSymbolAddress(&p, g_bcat);   float* p_bcat = (float*)p;
    cudaGetSymbolAddress(&p, g_deg);    float* p_deg = (float*)p;

    const int T = 256;
    cudaFuncSetAttribute(k_ewgemm, cudaFuncAttributeMaxDynamicSharedMemorySize, EW_SMEM);
    cudaFuncSetAttribute(k_nodegemm, cudaFuncAttributeMaxDynamicSharedMemorySize, NG_SMEM);
    cudaFuncSetAttribute(k_mgemm, cudaFuncAttributeMaxDynamicSharedMemorySize, NG_SMEM);

    // degree
    k_deg_zero<<<(cN + T - 1) / T, T>>>(p_deg);
    k_deg<<<(cE + T - 1) / T, T>>>(dst, p_deg);

    // lin0 -> h0 (also zeroes agg)
    k_lin0<<<(cN * cD + T - 1) / T, T>>>(x, lin0_w, lin0_b, p_h0, p_agg);

    // edge net + preps
    k_edge1<<<(cE * (cH / 2) + T - 1) / T, T>>>(ea, net_w1, net_b1, p_hrh);
    k_prepB<<<(cH * cDSQ + T - 1) / T, T>>>(net_w2, p_w2T);
    k_prepW<<<(cD * 4 * cD + T - 1) / T, T>>>(conv_root, gru_w_hh, gru_b_hh, p_Wcat, p_bcat);
    {
        dim3 grid(cDSQ / 64, (cE + 127) / 128);   // 64 x 313
        k_ewgemm<<<grid, 256, EW_SMEM>>>(p_hrh, p_w2T, net_b2, p_ewh);
    }

    // 3 message-passing steps
    for (int s = 0; s < 3; s++) {
        float* cur = (s & 1) ? p_h1 : p_h0;
        float* nxt = (s & 1) ? p_h0 : p_h1;

        {
            dim3 blk(32, 8);
            k_msg<<<(cE * 2 + 7) / 8, blk>>>(cur, p_ewh, src, dst, p_agg);
        }
        {
            dim3 grid(4, (cN + 127) / 128);
            k_nodegemm<<<grid, 128, NG_SMEM>>>(cN, 4 * cD, cur, p_Wcat, p_bcat, p_CG, 4 * cD);
        }
        {
            dim3 grid(3, (cN + 127) / 128);
            k_mgemm<<<grid, 128, NG_SMEM>>>(cN, 3 * cD, p_agg, p_CG, p_deg, conv_bias,
                                            gru_w_ih, gru_b_ih, p_G1, 3 * cD);
        }
        k_gate<<<(cN * cD + T - 1) / T, T>>>(p_G1, p_CG, cur, nxt, p_agg);
    }
    float* p_hfin = p_h1;

    // fused Set2Set (3 iterations) + lin1
    k_set2set<<<cB, 128>>>(p_hfin, batch, lstm_w_ih, lstm_w_hh, lstm_b_ih, lstm_b_hh,
                           lin1_w, lin1_b, out);
}

// round 14
// speedup vs baseline: 1.0992x; 1.0992x over previous
#include <cuda_runtime.h>
#include <cuda_fp16.h>
#include <math.h>
#include <stdint.h>

// ---------------- problem constants ----------------
#define cN 10000
#define cE 40000
#define cD 64
#define cB 512
#define cFIN 11
#define cEF 5
#define cH 128
#define cDSQ 4096

// ---------------- device scratch ----------------
__device__ float g_h0[cN * cD];
__device__ float g_h1[cN * cD];
__device__ __half g_hreluh[cE * cH];          // 10 MB fp16 edge-net hidden
__device__ __half g_w2T[cDSQ * cH];           // 1 MB fp16 transposed [n][k]
__device__ __half g_ewh[(size_t)cE * cDSQ];   // 320 MB fp16 edge weights (bias folded in)
__device__ float g_agg[cN * cD];
__device__ float g_CG[cN * 4 * cD];           // [N,256] = [croot | G2]
__device__ float g_G1[cN * 3 * cD];
__device__ float g_Wcat[cD * 4 * cD];         // [64,256] = [conv_root | gru_w_hh]
__device__ float g_bcat[4 * cD];
__device__ float g_deg[cN];

// ---------------- helpers ----------------
__device__ __forceinline__ float sigm(float x) { return 1.0f / (1.0f + expf(-x)); }

__device__ __forceinline__ uint32_t f2tf32(float f) {
    uint32_t u;
    asm("cvt.rna.tf32.f32 %0, %1;" : "=r"(u) : "f"(f));
    return u;
}
__device__ __forceinline__ void mma_tf32(float* d, const uint32_t* a, const uint32_t* b) {
    asm volatile(
        "mma.sync.aligned.m16n8k8.row.col.f32.tf32.tf32.f32 "
        "{%0,%1,%2,%3}, {%4,%5,%6,%7}, {%8,%9}, {%0,%1,%2,%3};"
        : "+f"(d[0]), "+f"(d[1]), "+f"(d[2]), "+f"(d[3])
        : "r"(a[0]), "r"(a[1]), "r"(a[2]), "r"(a[3]), "r"(b[0]), "r"(b[1]));
}
__device__ __forceinline__ void mma_f16(float* d, const uint32_t* a, const uint32_t* b) {
    asm volatile(
        "mma.sync.aligned.m16n8k16.row.col.f32.f16.f16.f32 "
        "{%0,%1,%2,%3}, {%4,%5,%6,%7}, {%8,%9}, {%0,%1,%2,%3};"
        : "+f"(d[0]), "+f"(d[1]), "+f"(d[2]), "+f"(d[3])
        : "r"(a[0]), "r"(a[1]), "r"(a[2]), "r"(a[3]), "r"(b[0]), "r"(b[1]));
}
__device__ __forceinline__ void cp16(void* smem, const void* gmem) {
    uint32_t s = (uint32_t)__cvta_generic_to_shared(smem);
    asm volatile("cp.async.ca.shared.global [%0], [%1], 16;" :: "r"(s), "l"(gmem));
}
__device__ __forceinline__ void stcs_h2(__half2* addr, __half2 v) {
    uint32_t b = *(uint32_t*)&v;
    asm volatile("st.global.cs.b32 [%0], %1;" :: "l"(addr), "r"(b) : "memory");
}

// ---------------- small kernels ----------------
__global__ void k_deg_zero(float* deg) {
    int i = blockIdx.x * blockDim.x + threadIdx.x;
    if (i < cN) deg[i] = 0.0f;
}
__global__ void k_deg(const int* __restrict__ dst, float* deg) {
    int e = blockIdx.x * blockDim.x + threadIdx.x;
    if (e < cE) atomicAdd(&deg[dst[e]], 1.0f);
}
// lin0 -> h0; also zero agg for step 0
__global__ void k_lin0(const float* __restrict__ x, const float* __restrict__ w,
                       const float* __restrict__ b, float* __restrict__ h0,
                       float* __restrict__ agg) {
    int idx = blockIdx.x * blockDim.x + threadIdx.x;
    if (idx >= cN * cD) return;
    int n = idx >> 6, d = idx & 63;
    float acc = b[d];
    const float* xr = x + n * cFIN;
#pragma unroll
    for (int i = 0; i < cFIN; i++) acc += xr[i] * w[i * cD + d];
    h0[idx] = fmaxf(acc, 0.0f);
    agg[idx] = 0.0f;
}
// edge-net layer 1, fp16 output, 2 outputs per thread
__global__ void k_edge1(const float* __restrict__ ea, const float* __restrict__ w1,
                        const float* __restrict__ b1, __half* __restrict__ hrelu) {
    int idx = blockIdx.x * blockDim.x + threadIdx.x;
    if (idx >= cE * (cH / 2)) return;
    int e = idx >> 6, j2 = (idx & 63) * 2;
    float acc0 = b1[j2], acc1 = b1[j2 + 1];
    const float* er = ea + e * cEF;
#pragma unroll
    for (int i = 0; i < cEF; i++) {
        float ev = er[i];
        float2 wp = *(const float2*)(w1 + i * cH + j2);
        acc0 += ev * wp.x;
        acc1 += ev * wp.y;
    }
    *(__half2*)(hrelu + (size_t)e * cH + j2) =
        __floats2half2_rn(fmaxf(acc0, 0.0f), fmaxf(acc1, 0.0f));
}
// w2T[n][k] = half(w2[k][n])
__global__ void k_prepB(const float* __restrict__ w2, __half* __restrict__ BT) {
    int idx = blockIdx.x * blockDim.x + threadIdx.x;
    if (idx >= cH * cDSQ) return;
    int n = idx >> 7, k = idx & 127;
    BT[idx] = __float2half(w2[(size_t)k * cDSQ + n]);
}
// Wcat [64][256] = [conv_root | gru_w_hh]; bcat [256] = [0 | gru_b_hh]
__global__ void k_prepW(const float* __restrict__ wroot, const float* __restrict__ whh,
                        const float* __restrict__ bhh,
                        float* __restrict__ Wcat, float* __restrict__ bcat) {
    int idx = blockIdx.x * blockDim.x + threadIdx.x;
    if (idx < cD * 4 * cD) {
        int k = idx >> 8, col = idx & 255;
        Wcat[idx] = (col < cD) ? wroot[k * cD + col] : whh[k * 3 * cD + (col - cD)];
    }
    if (idx < 4 * cD) bcat[idx] = (idx < cD) ? 0.0f : bhh[idx - cD];
}

// -------- fp16 tensor GEMM for ew: half C[E,4096] = A[E,128] @ B[128,4096] + bias --------
// CTA tile 128x128, full K resident, 8 warps (2x4), warp tile 64x32.
// Inner loop restructured (bf once per ks, af per mt) -> live regs ~100, fits 2 CTAs/SM.
#define EW_SMEM (128 * 136 * 2 * 2)
__global__ void __launch_bounds__(256, 2) k_ewgemm(const __half* __restrict__ Ah,
                                                   const __half* __restrict__ BTh,
                                                   const float* __restrict__ bias,
                                                   __half* __restrict__ C) {
    extern __shared__ __half ew_sm[];
    __half* As_h = ew_sm;                 // [128][136]
    __half* Bs_h = ew_sm + 128 * 136;     // [128][136]

    const int tid = threadIdx.x;
    const int warp = tid >> 5, lane = tid & 31;
    const int wm = warp >> 2, wn = warp & 3;
    const int g = lane >> 2, c = lane & 3;
    const int rowBase = blockIdx.y * 128;
    const int colBase = blockIdx.x * 128;

#pragma unroll
    for (int it = 0; it < 8; it++) {
        int idx = tid + it * 256;
        int row = idx >> 4, q = idx & 15;
        int grow = rowBase + row;
        __half* dstp = As_h + row * 136 + q * 8;
        if (grow < cE) cp16(dstp, Ah + (size_t)grow * cH + q * 8);
        else *(uint4*)dstp = make_uint4(0u, 0u, 0u, 0u);
    }
#pragma unroll
    for (int it = 0; it < 8; it++) {
        int idx = tid + it * 256;
        int n = idx >> 4, q = idx & 15;
        cp16(Bs_h + n * 136 + q * 8, BTh + (size_t)(colBase + n) * cH + q * 8);
    }
    asm volatile("cp.async.commit_group;");
    asm volatile("cp.async.wait_group 0;");
    __syncthreads();

    float acc[4][4][4];
#pragma unroll
    for (int mt = 0; mt < 4; mt++)
#pragma unroll
        for (int nt = 0; nt < 4; nt++)
#pragma unroll
            for (int j = 0; j < 4; j++) acc[mt][nt][j] = 0.0f;

#pragma unroll
    for (int ks = 0; ks < 8; ks++) {
        const int k0 = ks * 16;
        uint32_t bf[4][2];
#pragma unroll
        for (int nt = 0; nt < 4; nt++) {
            int n = wn * 32 + nt * 8 + g;
            bf[nt][0] = *(const uint32_t*)&Bs_h[n * 136 + k0 + 2 * c];
            bf[nt][1] = *(const uint32_t*)&Bs_h[n * 136 + k0 + 2 * c + 8];
        }
#pragma unroll
        for (int mt = 0; mt < 4; mt++) {
            int r = wm * 64 + mt * 16 + g;
            uint32_t af[4];
            af[0] = *(const uint32_t*)&As_h[r * 136 + k0 + 2 * c];
            af[1] = *(const uint32_t*)&As_h[(r + 8) * 136 + k0 + 2 * c];
            af[2] = *(const uint32_t*)&As_h[r * 136 + k0 + 2 * c + 8];
            af[3] = *(const uint32_t*)&As_h[(r + 8) * 136 + k0 + 2 * c + 8];
#pragma unroll
            for (int nt = 0; nt < 4; nt++)
                mma_f16(acc[mt][nt], af, bf[nt]);
        }
    }

#pragma unroll
    for (int mt = 0; mt < 4; mt++) {
        int r0 = rowBase + wm * 64 + mt * 16 + g;
#pragma unroll
        for (int nt = 0; nt < 4; nt++) {
            int cc = colBase + wn * 32 + nt * 8 + c * 2;
            float b0 = bias[cc], b1 = bias[cc + 1];
            if (r0 < cE)
                stcs_h2((__half2*)(C + (size_t)r0 * cDSQ + cc),
                        __floats2half2_rn(acc[mt][nt][0] + b0, acc[mt][nt][1] + b1));
            if (r0 + 8 < cE)
                stcs_h2((__half2*)(C + (size_t)(r0 + 8) * cDSQ + cc),
                        __floats2half2_rn(acc[mt][nt][2] + b0, acc[mt][nt][3] + b1));
        }
    }
}

// -------- TF32 node GEMM core --------
#define NG_SMEM (64 * 132 * 4 + 64 * 68 * 4)

__device__ __forceinline__ void nodegemm_core(
    uint32_t (*As)[132], uint32_t (*Bs)[68],
    int M, int ldb, const float* __restrict__ Bw,
    const float* __restrict__ bias, float* __restrict__ Cp, int ldc,
    int rowBase, int colBase)
{
    const int tid = threadIdx.x;
    const int warp = tid >> 5, lane = tid & 31;
    const int g = lane >> 2, c = lane & 3;

    {
        int kr = tid >> 1, half = tid & 1;
        const float4* br = (const float4*)(Bw + (size_t)kr * ldb + colBase + half * 32);
#pragma unroll
        for (int q = 0; q < 8; q++) {
            float4 v = br[q];
            int nq = half * 8 + q;
            uint4 u;
            u.x = f2tf32(v.x); u.y = f2tf32(v.y); u.z = f2tf32(v.z); u.w = f2tf32(v.w);
            *(uint4*)&Bs[kr][nq * 4] = u;
        }
    }
    __syncthreads();

    float acc[2][8][4];
#pragma unroll
    for (int mt = 0; mt < 2; mt++)
#pragma unroll
        for (int nt = 0; nt < 8; nt++)
#pragma unroll
            for (int j = 0; j < 4; j++) acc[mt][nt][j] = 0.0f;

    const int r0 = warp * 32;
#pragma unroll
    for (int k0 = 0; k0 < 64; k0 += 8) {
        uint32_t af[2][4];
#pragma unroll
        for (int mt = 0; mt < 2; mt++) {
            int r = r0 + mt * 16 + g;
            af[mt][0] = As[k0 + c][r];
            af[mt][1] = As[k0 + c][r + 8];
            af[mt][2] = As[k0 + c + 4][r];
            af[mt][3] = As[k0 + c + 4][r + 8];
        }
#pragma unroll
        for (int nt = 0; nt < 8; nt++) {
            uint32_t bf[2];
            bf[0] = Bs[k0 + c][nt * 8 + g];
            bf[1] = Bs[k0 + c + 4][nt * 8 + g];
            mma_tf32(acc[0][nt], af[0], bf);
            mma_tf32(acc[1][nt], af[1], bf);
        }
    }

#pragma unroll
    for (int mt = 0; mt < 2; mt++) {
        int rr0 = rowBase + r0 + mt * 16 + g;
        int rr1 = rr0 + 8;
#pragma unroll
        for (int nt = 0; nt < 8; nt++) {
            int cc = colBase + nt * 8 + c * 2;
            float b0 = bias ? bias[cc] : 0.0f;
            float b1 = bias ? bias[cc + 1] : 0.0f;
            if (rr0 < M) {
                float2 v = make_float2(acc[mt][nt][0] + b0, acc[mt][nt][1] + b1);
                *(float2*)(Cp + (size_t)rr0 * ldc + cc) = v;
            }
            if (rr1 < M) {
                float2 v = make_float2(acc[mt][nt][2] + b0, acc[mt][nt][3] + b1);
                *(float2*)(Cp + (size_t)rr1 * ldc + cc) = v;
            }
        }
    }
}

__global__ void __launch_bounds__(128) k_nodegemm(int M, int ldb,
                                                  const float* __restrict__ A,
                                                  const float* __restrict__ Bw,
                                                  const float* __restrict__ bias,
                                                  float* __restrict__ Cp, int ldc) {
    extern __shared__ uint32_t ng_sm[];
    uint32_t (*As)[132] = (uint32_t (*)[132])ng_sm;
    uint32_t (*Bs)[68]  = (uint32_t (*)[68])(ng_sm + 64 * 132);
    const int tid = threadIdx.x;
    const int rowBase = blockIdx.y * 128;
    {
        int grow = rowBase + tid;
        if (grow < M) {
            const float4* ar = (const float4*)(A + (size_t)grow * cD);
#pragma unroll
            for (int q = 0; q < 16; q++) {
                float4 v = ar[q];
                As[q * 4 + 0][tid] = f2tf32(v.x);
                As[q * 4 + 1][tid] = f2tf32(v.y);
                As[q * 4 + 2][tid] = f2tf32(v.z);
                As[q * 4 + 3][tid] = f2tf32(v.w);
            }
        } else {
#pragma unroll
            for (int q = 0; q < 64; q++) As[q][tid] = 0u;
        }
    }
    nodegemm_core(As, Bs, M, ldb, Bw, bias, Cp, ldc, rowBase, blockIdx.x * 64);
}

__global__ void __launch_bounds__(128) k_mgemm(int M, int ldb,
                                               const float* __restrict__ agg,
                                               const float* __restrict__ CG,
                                               const float* __restrict__ deg,
                                               const float* __restrict__ cbias,
                                               const float* __restrict__ Bw,
                                               const float* __restrict__ bias,
                                               float* __restrict__ Cp, int ldc) {
    extern __shared__ uint32_t ng_sm[];
    uint32_t (*As)[132] = (uint32_t (*)[132])ng_sm;
    uint32_t (*Bs)[68]  = (uint32_t (*)[68])(ng_sm + 64 * 132);
    const int tid = threadIdx.x;
    const int rowBase = blockIdx.y * 128;
    {
        int grow = rowBase + tid;
        if (grow < M) {
            float inv = 1.0f / fmaxf(deg[grow], 1.0f);
            const float4* ag = (const float4*)(agg + (size_t)grow * cD);
            const float4* cg = (const float4*)(CG + (size_t)grow * 4 * cD);
            const float4* cb = (const float4*)(cbias);
#pragma unroll
            for (int q = 0; q < 16; q++) {
                float4 a = ag[q], cr = cg[q], bb = cb[q];
                As[q * 4 + 0][tid] = f2tf32(fmaxf(a.x * inv + cr.x + bb.x, 0.0f));
                As[q * 4 + 1][tid] = f2tf32(fmaxf(a.y * inv + cr.y + bb.y, 0.0f));
                As[q * 4 + 2][tid] = f2tf32(fmaxf(a.z * inv + cr.z + bb.z, 0.0f));
                As[q * 4 + 3][tid] = f2tf32(fmaxf(a.w * inv + cr.w + bb.w, 0.0f));
            }
        } else {
#pragma unroll
            for (int q = 0; q < 64; q++) As[q][tid] = 0u;
        }
    }
    nodegemm_core(As, Bs, M, ldb, Bw, bias, Cp, ldc, rowBase, blockIdx.x * 64);
}

// -------- per-edge matvec + scatter: 2 warps per edge (row-split), streaming loads --------
__global__ void k_msg(const float* __restrict__ out, const __half* __restrict__ ew,
                      const int* __restrict__ src, const int* __restrict__ dst,
                      float* __restrict__ agg) {
    int w = blockIdx.x * blockDim.y + threadIdx.y;   // global warp id
    int e = w >> 1;
    if (e >= cE) return;
    int half = w & 1;                                 // row half
    int lane = threadIdx.x;
    int s = src[e];
    float v = __ldg(out + (size_t)s * cD + half * 32 + lane);
    const uint4* wp = (const uint4*)(ew + (size_t)e * cDSQ);
    const int rl = lane >> 3, cl8 = lane & 7;
    const int rbase = half * 32;
    float acc[8];
#pragma unroll
    for (int q = 0; q < 8; q++) acc[q] = 0.0f;

#pragma unroll
    for (int j = 0; j < 8; j++) {
        int rloc = j * 4 + rl;
        float vv = __shfl_sync(0xffffffffu, v, rloc);
        uint4 u = __ldcs(&wp[(rbase + rloc) * 8 + cl8]);
        __half2* h2 = (__half2*)&u;
#pragma unroll
        for (int q = 0; q < 4; q++) {
            float2 f = __half22float2(h2[q]);
            acc[q * 2]     += vv * f.x;
            acc[q * 2 + 1] += vv * f.y;
        }
    }
#pragma unroll
    for (int off = 8; off <= 16; off <<= 1)
#pragma unroll
        for (int q = 0; q < 8; q++)
            acc[q] += __shfl_xor_sync(0xffffffffu, acc[q], off);

    int dn = dst[e];
    int col = cl8 * 8 + rl * 2;
    atomicAdd(&agg[(size_t)dn * cD + col],     acc[rl * 2]);
    atomicAdd(&agg[(size_t)dn * cD + col + 1], acc[rl * 2 + 1]);
}

// GRU gates; also zeroes agg for the next step
__global__ void k_gate(const float* __restrict__ G1, const float* __restrict__ CG,
                       const float* __restrict__ h, float* __restrict__ hn,
                       float* __restrict__ agg) {
    int idx = blockIdx.x * blockDim.x + threadIdx.x;
    if (idx >= cN * cD) return;
    int n = idx >> 6, d = idx & 63;
    const float* g1 = G1 + (size_t)n * 3 * cD;
    const float* g2 = CG + (size_t)n * 4 * cD + cD;
    float r = sigm(g1[d] + g2[d]);
    float z = sigm(g1[cD + d] + g2[cD + d]);
    float nn = tanhf(g1[2 * cD + d] + r * g2[2 * cD + d]);
    hn[idx] = (1.0f - z) * nn + z * h[idx];
    agg[idx] = 0.0f;
}

// -------- fused Set2Set (3 iterations) + final lin1 --------
__global__ void __launch_bounds__(128) k_set2set(
    const float* __restrict__ hfin, const int* __restrict__ batch,
    const float* __restrict__ w_ih, const float* __restrict__ w_hh,
    const float* __restrict__ b_ih, const float* __restrict__ b_hh,
    const float* __restrict__ l1w, const float* __restrict__ l1b,
    float* __restrict__ outp)
{
    const int b = blockIdx.x;
    const int tid = threadIdx.x, warp = tid >> 5, lane = tid & 31;
    __shared__ float s_qstar[128], s_g[256], s_q[64], s_cl[64], s_rvec[64];
    __shared__ float s_wmax[4], s_wsum[4];
    __shared__ float s_gmax, s_gsum;
    __shared__ int s_s, s_e;

    if (tid == 0) {
        int lo = 0, hi = cN;
        while (lo < hi) { int mid = (lo + hi) >> 1; if (batch[mid] < b) lo = mid + 1; else hi = mid; }
        s_s = lo;
        hi = cN;
        while (lo < hi) { int mid = (lo + hi) >> 1; if (batch[mid] < b + 1) lo = mid + 1; else hi = mid; }
        s_e = lo;
    }
    s_qstar[tid] = 0.0f;
    if (tid < 64) { s_q[tid] = 0.0f; s_cl[tid] = 0.0f; }
    __syncthreads();

    for (int t = 0; t < 3; t++) {
        float g0 = b_ih[tid] + b_hh[tid];
        float g1 = b_ih[tid + 128] + b_hh[tid + 128];
#pragma unroll 4
        for (int k = 0; k < 128; k++) {
            float qv = s_qstar[k];
            g0 += qv * w_ih[k * 256 + tid];
            g1 += qv * w_ih[k * 256 + tid + 128];
        }
#pragma unroll 4
        for (int k = 0; k < 64; k++) {
            float hv = s_q[k];
            g0 += hv * w_hh[k * 256 + tid];
            g1 += hv * w_hh[k * 256 + tid + 128];
        }
        s_g[tid] = g0; s_g[tid + 128] = g1;
        __syncthreads();
        if (tid < 64) {
            float ig = sigm(s_g[tid]), fg = sigm(s_g[64 + tid]);
            float gg = tanhf(s_g[128 + tid]), og = sigm(s_g[192 + tid]);
            float c = fg * s_cl[tid] + ig * gg;
            s_cl[tid] = c;
            s_q[tid] = og * tanhf(c);
            s_rvec[tid] = 0.0f;
        }
        __syncthreads();

        const int ns = s_s, ne = s_e;
        float wmax = -1e30f;
        for (int n = ns + warp; n < ne; n += 4) {
            const float* o = hfin + (size_t)n * cD;
            float d = o[lane] * s_q[lane] + o[32 + lane] * s_q[32 + lane];
#pragma unroll
            for (int off = 16; off; off >>= 1) d += __shfl_xor_sync(0xffffffffu, d, off);
            wmax = fmaxf(wmax, d);
        }
        if (lane == 0) s_wmax[warp] = wmax;
        __syncthreads();
        if (tid == 0)
            s_gmax = fmaxf(fmaxf(s_wmax[0], s_wmax[1]), fmaxf(s_wmax[2], s_wmax[3]));
        __syncthreads();
        const float gmax = s_gmax;

        float wsum = 0.0f, rv0 = 0.0f, rv1 = 0.0f;
        for (int n = ns + warp; n < ne; n += 4) {
            const float* o = hfin + (size_t)n * cD;
            float d = o[lane] * s_q[lane] + o[32 + lane] * s_q[32 + lane];
#pragma unroll
            for (int off = 16; off; off >>= 1) d += __shfl_xor_sync(0xffffffffu, d, off);
            float ee = expf(d - gmax);
            wsum += ee;
            rv0 += ee * o[lane];
            rv1 += ee * o[32 + lane];
        }
        if (lane == 0) s_wsum[warp] = wsum;
        atomicAdd(&s_rvec[lane], rv0);
        atomicAdd(&s_rvec[32 + lane], rv1);
        __syncthreads();
        if (tid == 0) s_gsum = s_wsum[0] + s_wsum[1] + s_wsum[2] + s_wsum[3];
        __syncthreads();

        if (tid < 64) s_qstar[tid] = s_q[tid];
        else {
            float denom = s_gsum;
            s_qstar[tid] = (denom > 0.0f) ? s_rvec[tid - 64] / denom : 0.0f;
        }
        __syncthreads();
    }

    if (tid < 64) {
        float acc = l1b[tid];
#pragma unroll 4
        for (int k = 0; k < 128; k++) acc += s_qstar[k] * l1w[k * cD + tid];
        outp[b * cD + tid] = fmaxf(acc, 0.0f);
    }
}

// ---------------- launch ----------------
extern "C" void kernel_launch(void* const* d_in, const int* in_sizes, int n_in,
                              void* d_out, int out_size) {
    const float* x        = (const float*)d_in[0];
    const float* ea       = (const float*)d_in[1];
    const int*   ei       = (const int*)d_in[2];
    const int*   batch    = (const int*)d_in[3];
    const float* lin0_w   = (const float*)d_in[4];
    const float* lin0_b   = (const float*)d_in[5];
    const float* net_w1   = (const float*)d_in[6];
    const float* net_b1   = (const float*)d_in[7];
    const float* net_w2   = (const float*)d_in[8];
    const float* net_b2   = (const float*)d_in[9];
    const float* conv_root= (const float*)d_in[10];
    const float* conv_bias= (const float*)d_in[11];
    const float* gru_w_ih = (const float*)d_in[12];
    const float* gru_w_hh = (const float*)d_in[13];
    const float* gru_b_ih = (const float*)d_in[14];
    const float* gru_b_hh = (const float*)d_in[15];
    const float* lstm_w_ih= (const float*)d_in[16];
    const float* lstm_w_hh= (const float*)d_in[17];
    const float* lstm_b_ih= (const float*)d_in[18];
    const float* lstm_b_hh= (const float*)d_in[19];
    const float* lin1_w   = (const float*)d_in[20];
    const float* lin1_b   = (const float*)d_in[21];
    float* out = (float*)d_out;

    const int* src = ei;
    const int* dst = ei + cE;

    void* p;
    cudaGetSymbolAddress(&p, g_h0);     float* p_h0 = (float*)p;
    cudaGetSymbolAddress(&p, g_h1);     float* p_h1 = (float*)p;
    cudaGetSymbolAddress(&p, g_hreluh); __half* p_hrh = (__half*)p;
    cudaGetSymbolAddress(&p, g_w2T);    __half* p_w2T = (__half*)p;
    cudaGetSymbolAddress(&p, g_ewh);    __half* p_ewh = (__half*)p;
    cudaGetSymbolAddress(&p, g_agg);    float* p_agg = (float*)p;
    cudaGetSymbolAddress(&p, g_CG);     float* p_CG = (float*)p;
    cudaGetSymbolAddress(&p, g_G1);     float* p_G1 = (float*)p;
    cudaGetSymbolAddress(&p, g_Wcat);   float* p_Wcat = (float*)p;
    cudaGetSymbolAddress(&p, g_bcat);   float* p_bcat = (float*)p;
    cudaGetSymbolAddress(&p, g_deg);    float* p_deg = (float*)p;

    const int T = 256;
    cudaFuncSetAttribute(k_ewgemm, cudaFuncAttributeMaxDynamicSharedMemorySize, EW_SMEM);
    cudaFuncSetAttribute(k_nodegemm, cudaFuncAttributeMaxDynamicSharedMemorySize, NG_SMEM);
    cudaFuncSetAttribute(k_mgemm, cudaFuncAttributeMaxDynamicSharedMemorySize, NG_SMEM);

    // degree
    k_deg_zero<<<(cN + T - 1) / T, T>>>(p_deg);
    k_deg<<<(cE + T - 1) / T, T>>>(dst, p_deg);

    // lin0 -> h0 (also zeroes agg)
    k_lin0<<<(cN * cD + T - 1) / T, T>>>(x, lin0_w, lin0_b, p_h0, p_agg);

    // edge net + preps
    k_edge1<<<(cE * (cH / 2) + T - 1) / T, T>>>(ea, net_w1, net_b1, p_hrh);
    k_prepB<<<(cH * cDSQ + T - 1) / T, T>>>(net_w2, p_w2T);
    k_prepW<<<(cD * 4 * cD + T - 1) / T, T>>>(conv_root, gru_w_hh, gru_b_hh, p_Wcat, p_bcat);
    {
        dim3 grid(cDSQ / 128, (cE + 127) / 128);   // 32 x 313
        k_ewgemm<<<grid, 256, EW_SMEM>>>(p_hrh, p_w2T, net_b2, p_ewh);
    }

    // 3 message-passing steps
    for (int s = 0; s < 3; s++) {
        float* cur = (s & 1) ? p_h1 : p_h0;
        float* nxt = (s & 1) ? p_h0 : p_h1;

        {
            dim3 blk(32, 8);
            k_msg<<<(cE * 2 + 7) / 8, blk>>>(cur, p_ewh, src, dst, p_agg);
        }
        {
            dim3 grid(4, (cN + 127) / 128);
            k_nodegemm<<<grid, 128, NG_SMEM>>>(cN, 4 * cD, cur, p_Wcat, p_bcat, p_CG, 4 * cD);
        }
        {
            dim3 grid(3, (cN + 127) / 128);
            k_mgemm<<<grid, 128, NG_SMEM>>>(cN, 3 * cD, p_agg, p_CG, p_deg, conv_bias,
                                            gru_w_ih, gru_b_ih, p_G1, 3 * cD);
        }
        k_gate<<<(cN * cD + T - 1) / T, T>>>(p_G1, p_CG, cur, nxt, p_agg);
    }
    float* p_hfin = p_h1;

    // fused Set2Set (3 iterations) + lin1
    k_set2set<<<cB, 128>>>(p_hfin, batch, lstm_w_ih, lstm_w_hh, lstm_b_ih, lstm_b_hh,
                           lin1_w, lin1_b, out);
}

// round 15
// speedup vs baseline: 1.1098x; 1.0097x over previous
#include <cuda_runtime.h>
#include <cuda_fp16.h>
#include <math.h>
#include <stdint.h>

// ---------------- problem constants ----------------
#define cN 10000
#define cE 40000
#define cD 64
#define cB 512
#define cFIN 11
#define cEF 5
#define cH 128
#define cDSQ 4096

// ---------------- device scratch ----------------
__device__ float g_h0[cN * cD];
__device__ float g_h1[cN * cD];
__device__ __half g_hreluh[cE * cH];          // 10 MB fp16 edge-net hidden
__device__ __half g_w2T[cDSQ * cH];           // 1 MB fp16 transposed [n][k]
__device__ __half g_ewh[(size_t)cE * cDSQ];   // 320 MB fp16 edge weights (bias folded in)
__device__ float g_agg[cN * cD];
__device__ float g_CG[cN * 4 * cD];           // [N,256] = [croot | G2]
__device__ float g_G1[cN * 3 * cD];
__device__ float g_Wcat[cD * 4 * cD];         // [64,256] = [conv_root | gru_w_hh]
__device__ float g_bcat[4 * cD];
__device__ float g_deg[cN];

// ---------------- helpers ----------------
__device__ __forceinline__ float sigm(float x) { return 1.0f / (1.0f + expf(-x)); }

__device__ __forceinline__ uint32_t f2tf32(float f) {
    uint32_t u;
    asm("cvt.rna.tf32.f32 %0, %1;" : "=r"(u) : "f"(f));
    return u;
}
__device__ __forceinline__ void mma_tf32(float* d, const uint32_t* a, const uint32_t* b) {
    asm volatile(
        "mma.sync.aligned.m16n8k8.row.col.f32.tf32.tf32.f32 "
        "{%0,%1,%2,%3}, {%4,%5,%6,%7}, {%8,%9}, {%0,%1,%2,%3};"
        : "+f"(d[0]), "+f"(d[1]), "+f"(d[2]), "+f"(d[3])
        : "r"(a[0]), "r"(a[1]), "r"(a[2]), "r"(a[3]), "r"(b[0]), "r"(b[1]));
}
__device__ __forceinline__ void mma_f16(float* d, const uint32_t* a, const uint32_t* b) {
    asm volatile(
        "mma.sync.aligned.m16n8k16.row.col.f32.f16.f16.f32 "
        "{%0,%1,%2,%3}, {%4,%5,%6,%7}, {%8,%9}, {%0,%1,%2,%3};"
        : "+f"(d[0]), "+f"(d[1]), "+f"(d[2]), "+f"(d[3])
        : "r"(a[0]), "r"(a[1]), "r"(a[2]), "r"(a[3]), "r"(b[0]), "r"(b[1]));
}
__device__ __forceinline__ void cp16(void* smem, const void* gmem) {
    uint32_t s = (uint32_t)__cvta_generic_to_shared(smem);
    asm volatile("cp.async.ca.shared.global [%0], [%1], 16;" :: "r"(s), "l"(gmem));
}
__device__ __forceinline__ void stcs_h2(__half2* addr, __half2 v) {
    uint32_t b = *(uint32_t*)&v;
    asm volatile("st.global.cs.b32 [%0], %1;" :: "l"(addr), "r"(b) : "memory");
}

// ---------------- fused init kernel: edge1 | lin0 | prepB | prepW | deg_zero ----------------
#define UB_EDGE1 10000
#define UB_LIN0  2500
#define UB_PREPB 512
#define UB_PREPW 65
#define UB_DEGZ  40
#define UB_TOTAL (UB_EDGE1 + UB_LIN0 + UB_PREPB + UB_PREPW + UB_DEGZ)

__global__ void __launch_bounds__(256) k_init(
    const float* __restrict__ ea, const float* __restrict__ w1,
    const float* __restrict__ b1, __half* __restrict__ hrelu,
    const float* __restrict__ x, const float* __restrict__ l0w,
    const float* __restrict__ l0b, float* __restrict__ h0, float* __restrict__ agg,
    const float* __restrict__ w2, __half* __restrict__ BT,
    const float* __restrict__ wroot, const float* __restrict__ whh,
    const float* __restrict__ bhh, float* __restrict__ Wcat, float* __restrict__ bcat,
    float* __restrict__ deg)
{
    const int bx = blockIdx.x, tid = threadIdx.x;
    __shared__ float ts[32][33];

    if (bx < UB_EDGE1) {
        // edge-net layer 1: 2 outputs per thread
        int idx = bx * 256 + tid;
        int e = idx >> 6, j2 = (idx & 63) * 2;
        float acc0 = b1[j2], acc1 = b1[j2 + 1];
        const float* er = ea + e * cEF;
#pragma unroll
        for (int i = 0; i < cEF; i++) {
            float ev = er[i];
            float2 wp = *(const float2*)(w1 + i * cH + j2);
            acc0 += ev * wp.x;
            acc1 += ev * wp.y;
        }
        *(__half2*)(hrelu + (size_t)e * cH + j2) =
            __floats2half2_rn(fmaxf(acc0, 0.0f), fmaxf(acc1, 0.0f));
    } else if (bx < UB_EDGE1 + UB_LIN0) {
        // lin0 -> h0; zero agg
        int idx = (bx - UB_EDGE1) * 256 + tid;
        int n = idx >> 6, d = idx & 63;
        float acc = l0b[d];
        const float* xr = x + n * cFIN;
#pragma unroll
        for (int i = 0; i < cFIN; i++) acc += xr[i] * l0w[i * cD + d];
        h0[idx] = fmaxf(acc, 0.0f);
        agg[idx] = 0.0f;
    } else if (bx < UB_EDGE1 + UB_LIN0 + UB_PREPB) {
        // w2 [128][4096] fp32 -> BT [4096][128] fp16, 32x32 smem tile transpose
        int pb = bx - (UB_EDGE1 + UB_LIN0);
        int ktile = pb >> 7, ntile = pb & 127;
        int k0 = ktile * 32, n0 = ntile * 32;
        int c = tid & 31, rq = tid >> 5;        // 8 row-groups of 4
#pragma unroll
        for (int i = 0; i < 4; i++) {
            int r = rq * 4 + i;
            ts[r][c] = w2[(size_t)(k0 + r) * cDSQ + n0 + c];
        }
        __syncthreads();
#pragma unroll
        for (int i = 0; i < 4; i++) {
            int rn = rq * 4 + i;
            BT[(size_t)(n0 + rn) * cH + k0 + c] = __float2half(ts[c][rn]);
        }
    } else if (bx < UB_EDGE1 + UB_LIN0 + UB_PREPB + UB_PREPW) {
        int idx = (bx - (UB_EDGE1 + UB_LIN0 + UB_PREPB)) * 256 + tid;
        if (idx < cD * 4 * cD) {
            int k = idx >> 8, col = idx & 255;
            Wcat[idx] = (col < cD) ? wroot[k * cD + col] : whh[k * 3 * cD + (col - cD)];
        }
        if (idx < 4 * cD) bcat[idx] = (idx < cD) ? 0.0f : bhh[idx - cD];
    } else {
        int idx = (bx - (UB_EDGE1 + UB_LIN0 + UB_PREPB + UB_PREPW)) * 256 + tid;
        if (idx < cN) deg[idx] = 0.0f;
    }
}

__global__ void k_deg(const int* __restrict__ dst, float* deg) {
    int e = blockIdx.x * blockDim.x + threadIdx.x;
    if (e < cE) atomicAdd(&deg[dst[e]], 1.0f);
}

// -------- fp16 tensor GEMM for ew: half C[E,4096] = A[E,128] @ B[128,4096] + bias --------
#define EW_SMEM (128 * 136 * 2 * 2)
__global__ void __launch_bounds__(256, 2) k_ewgemm(const __half* __restrict__ Ah,
                                                   const __half* __restrict__ BTh,
                                                   const float* __restrict__ bias,
                                                   __half* __restrict__ C) {
    extern __shared__ __half ew_sm[];
    __half* As_h = ew_sm;                 // [128][136]
    __half* Bs_h = ew_sm + 128 * 136;     // [128][136]

    const int tid = threadIdx.x;
    const int warp = tid >> 5, lane = tid & 31;
    const int wm = warp >> 2, wn = warp & 3;
    const int g = lane >> 2, c = lane & 3;
    const int rowBase = blockIdx.y * 128;
    const int colBase = blockIdx.x * 128;

#pragma unroll
    for (int it = 0; it < 8; it++) {
        int idx = tid + it * 256;
        int row = idx >> 4, q = idx & 15;
        int grow = rowBase + row;
        __half* dstp = As_h + row * 136 + q * 8;
        if (grow < cE) cp16(dstp, Ah + (size_t)grow * cH + q * 8);
        else *(uint4*)dstp = make_uint4(0u, 0u, 0u, 0u);
    }
#pragma unroll
    for (int it = 0; it < 8; it++) {
        int idx = tid + it * 256;
        int n = idx >> 4, q = idx & 15;
        cp16(Bs_h + n * 136 + q * 8, BTh + (size_t)(colBase + n) * cH + q * 8);
    }
    asm volatile("cp.async.commit_group;");
    asm volatile("cp.async.wait_group 0;");
    __syncthreads();

    float acc[4][4][4];
#pragma unroll
    for (int mt = 0; mt < 4; mt++)
#pragma unroll
        for (int nt = 0; nt < 4; nt++)
#pragma unroll
            for (int j = 0; j < 4; j++) acc[mt][nt][j] = 0.0f;

#pragma unroll
    for (int ks = 0; ks < 8; ks++) {
        const int k0 = ks * 16;
        uint32_t bf[4][2];
#pragma unroll
        for (int nt = 0; nt < 4; nt++) {
            int n = wn * 32 + nt * 8 + g;
            bf[nt][0] = *(const uint32_t*)&Bs_h[n * 136 + k0 + 2 * c];
            bf[nt][1] = *(const uint32_t*)&Bs_h[n * 136 + k0 + 2 * c + 8];
        }
#pragma unroll
        for (int mt = 0; mt < 4; mt++) {
            int r = wm * 64 + mt * 16 + g;
            uint32_t af[4];
            af[0] = *(const uint32_t*)&As_h[r * 136 + k0 + 2 * c];
            af[1] = *(const uint32_t*)&As_h[(r + 8) * 136 + k0 + 2 * c];
            af[2] = *(const uint32_t*)&As_h[r * 136 + k0 + 2 * c + 8];
            af[3] = *(const uint32_t*)&As_h[(r + 8) * 136 + k0 + 2 * c + 8];
#pragma unroll
            for (int nt = 0; nt < 4; nt++)
                mma_f16(acc[mt][nt], af, bf[nt]);
        }
    }

#pragma unroll
    for (int mt = 0; mt < 4; mt++) {
        int r0 = rowBase + wm * 64 + mt * 16 + g;
#pragma unroll
        for (int nt = 0; nt < 4; nt++) {
            int cc = colBase + wn * 32 + nt * 8 + c * 2;
            float b0 = bias[cc], b1 = bias[cc + 1];
            if (r0 < cE)
                stcs_h2((__half2*)(C + (size_t)r0 * cDSQ + cc),
                        __floats2half2_rn(acc[mt][nt][0] + b0, acc[mt][nt][1] + b1));
            if (r0 + 8 < cE)
                stcs_h2((__half2*)(C + (size_t)(r0 + 8) * cDSQ + cc),
                        __floats2half2_rn(acc[mt][nt][2] + b0, acc[mt][nt][3] + b1));
        }
    }
}

// -------- TF32 node GEMM core --------
#define NG_SMEM (64 * 132 * 4 + 64 * 68 * 4)

__device__ __forceinline__ void nodegemm_core(
    uint32_t (*As)[132], uint32_t (*Bs)[68],
    int M, int ldb, const float* __restrict__ Bw,
    const float* __restrict__ bias, float* __restrict__ Cp, int ldc,
    int rowBase, int colBase)
{
    const int tid = threadIdx.x;
    const int warp = tid >> 5, lane = tid & 31;
    const int g = lane >> 2, c = lane & 3;

    {
        int kr = tid >> 1, half = tid & 1;
        const float4* br = (const float4*)(Bw + (size_t)kr * ldb + colBase + half * 32);
#pragma unroll
        for (int q = 0; q < 8; q++) {
            float4 v = br[q];
            int nq = half * 8 + q;
            uint4 u;
            u.x = f2tf32(v.x); u.y = f2tf32(v.y); u.z = f2tf32(v.z); u.w = f2tf32(v.w);
            *(uint4*)&Bs[kr][nq * 4] = u;
        }
    }
    __syncthreads();

    float acc[2][8][4];
#pragma unroll
    for (int mt = 0; mt < 2; mt++)
#pragma unroll
        for (int nt = 0; nt < 8; nt++)
#pragma unroll
            for (int j = 0; j < 4; j++) acc[mt][nt][j] = 0.0f;

    const int r0 = warp * 32;
#pragma unroll
    for (int k0 = 0; k0 < 64; k0 += 8) {
        uint32_t af[2][4];
#pragma unroll
        for (int mt = 0; mt < 2; mt++) {
            int r = r0 + mt * 16 + g;
            af[mt][0] = As[k0 + c][r];
            af[mt][1] = As[k0 + c][r + 8];
            af[mt][2] = As[k0 + c + 4][r];
            af[mt][3] = As[k0 + c + 4][r + 8];
        }
#pragma unroll
        for (int nt = 0; nt < 8; nt++) {
            uint32_t bf[2];
            bf[0] = Bs[k0 + c][nt * 8 + g];
            bf[1] = Bs[k0 + c + 4][nt * 8 + g];
            mma_tf32(acc[0][nt], af[0], bf);
            mma_tf32(acc[1][nt], af[1], bf);
        }
    }

#pragma unroll
    for (int mt = 0; mt < 2; mt++) {
        int rr0 = rowBase + r0 + mt * 16 + g;
        int rr1 = rr0 + 8;
#pragma unroll
        for (int nt = 0; nt < 8; nt++) {
            int cc = colBase + nt * 8 + c * 2;
            float b0 = bias ? bias[cc] : 0.0f;
            float b1 = bias ? bias[cc + 1] : 0.0f;
            if (rr0 < M) {
                float2 v = make_float2(acc[mt][nt][0] + b0, acc[mt][nt][1] + b1);
                *(float2*)(Cp + (size_t)rr0 * ldc + cc) = v;
            }
            if (rr1 < M) {
                float2 v = make_float2(acc[mt][nt][2] + b0, acc[mt][nt][3] + b1);
                *(float2*)(Cp + (size_t)rr1 * ldc + cc) = v;
            }
        }
    }
}

__global__ void __launch_bounds__(128) k_nodegemm(int M, int ldb,
                                                  const float* __restrict__ A,
                                                  const float* __restrict__ Bw,
                                                  const float* __restrict__ bias,
                                                  float* __restrict__ Cp, int ldc) {
    extern __shared__ uint32_t ng_sm[];
    uint32_t (*As)[132] = (uint32_t (*)[132])ng_sm;
    uint32_t (*Bs)[68]  = (uint32_t (*)[68])(ng_sm + 64 * 132);
    const int tid = threadIdx.x;
    const int rowBase = blockIdx.y * 128;
    {
        int grow = rowBase + tid;
        if (grow < M) {
            const float4* ar = (const float4*)(A + (size_t)grow * cD);
#pragma unroll
            for (int q = 0; q < 16; q++) {
                float4 v = ar[q];
                As[q * 4 + 0][tid] = f2tf32(v.x);
                As[q * 4 + 1][tid] = f2tf32(v.y);
                As[q * 4 + 2][tid] = f2tf32(v.z);
                As[q * 4 + 3][tid] = f2tf32(v.w);
            }
        } else {
#pragma unroll
            for (int q = 0; q < 64; q++) As[q][tid] = 0u;
        }
    }
    nodegemm_core(As, Bs, M, ldb, Bw, bias, Cp, ldc, rowBase, blockIdx.x * 64);
}

__global__ void __launch_bounds__(128) k_mgemm(int M, int ldb,
                                               const float* __restrict__ agg,
                                               const float* __restrict__ CG,
                                               const float* __restrict__ deg,
                                               const float* __restrict__ cbias,
                                               const float* __restrict__ Bw,
                                               const float* __restrict__ bias,
                                               float* __restrict__ Cp, int ldc) {
    extern __shared__ uint32_t ng_sm[];
    uint32_t (*As)[132] = (uint32_t (*)[132])ng_sm;
    uint32_t (*Bs)[68]  = (uint32_t (*)[68])(ng_sm + 64 * 132);
    const int tid = threadIdx.x;
    const int rowBase = blockIdx.y * 128;
    {
        int grow = rowBase + tid;
        if (grow < M) {
            float inv = 1.0f / fmaxf(deg[grow], 1.0f);
            const float4* ag = (const float4*)(agg + (size_t)grow * cD);
            const float4* cg = (const float4*)(CG + (size_t)grow * 4 * cD);
            const float4* cb = (const float4*)(cbias);
#pragma unroll
            for (int q = 0; q < 16; q++) {
                float4 a = ag[q], cr = cg[q], bb = cb[q];
                As[q * 4 + 0][tid] = f2tf32(fmaxf(a.x * inv + cr.x + bb.x, 0.0f));
                As[q * 4 + 1][tid] = f2tf32(fmaxf(a.y * inv + cr.y + bb.y, 0.0f));
                As[q * 4 + 2][tid] = f2tf32(fmaxf(a.z * inv + cr.z + bb.z, 0.0f));
                As[q * 4 + 3][tid] = f2tf32(fmaxf(a.w * inv + cr.w + bb.w, 0.0f));
            }
        } else {
#pragma unroll
            for (int q = 0; q < 64; q++) As[q][tid] = 0u;
        }
    }
    nodegemm_core(As, Bs, M, ldb, Bw, bias, Cp, ldc, rowBase, blockIdx.x * 64);
}

// -------- per-edge matvec + scatter: 2 warps per edge (row-split), streaming loads --------
__global__ void k_msg(const float* __restrict__ out, const __half* __restrict__ ew,
                      const int* __restrict__ src, const int* __restrict__ dst,
                      float* __restrict__ agg) {
    int w = blockIdx.x * blockDim.y + threadIdx.y;   // global warp id
    int e = w >> 1;
    if (e >= cE) return;
    int half = w & 1;
    int lane = threadIdx.x;
    int s = src[e];
    float v = __ldg(out + (size_t)s * cD + half * 32 + lane);
    const uint4* wp = (const uint4*)(ew + (size_t)e * cDSQ);
    const int rl = lane >> 3, cl8 = lane & 7;
    const int rbase = half * 32;
    float acc[8];
#pragma unroll
    for (int q = 0; q < 8; q++) acc[q] = 0.0f;

#pragma unroll
    for (int j = 0; j < 8; j++) {
        int rloc = j * 4 + rl;
        float vv = __shfl_sync(0xffffffffu, v, rloc);
        uint4 u = __ldcs(&wp[(rbase + rloc) * 8 + cl8]);
        __half2* h2 = (__half2*)&u;
#pragma unroll
        for (int q = 0; q < 4; q++) {
            float2 f = __half22float2(h2[q]);
            acc[q * 2]     += vv * f.x;
            acc[q * 2 + 1] += vv * f.y;
        }
    }
#pragma unroll
    for (int off = 8; off <= 16; off <<= 1)
#pragma unroll
        for (int q = 0; q < 8; q++)
            acc[q] += __shfl_xor_sync(0xffffffffu, acc[q], off);

    int dn = dst[e];
    int col = cl8 * 8 + rl * 2;
    atomicAdd(&agg[(size_t)dn * cD + col],     acc[rl * 2]);
    atomicAdd(&agg[(size_t)dn * cD + col + 1], acc[rl * 2 + 1]);
}

// GRU gates; also zeroes agg for the next step
__global__ void k_gate(const float* __restrict__ G1, const float* __restrict__ CG,
                       const float* __restrict__ h, float* __restrict__ hn,
                       float* __restrict__ agg) {
    int idx = blockIdx.x * blockDim.x + threadIdx.x;
    if (idx >= cN * cD) return;
    int n = idx >> 6, d = idx & 63;
    const float* g1 = G1 + (size_t)n * 3 * cD;
    const float* g2 = CG + (size_t)n * 4 * cD + cD;
    float r = sigm(g1[d] + g2[d]);
    float z = sigm(g1[cD + d] + g2[cD + d]);
    float nn = tanhf(g1[2 * cD + d] + r * g2[2 * cD + d]);
    hn[idx] = (1.0f - z) * nn + z * h[idx];
    agg[idx] = 0.0f;
}

// -------- fused Set2Set (3 iterations) + final lin1 --------
__global__ void __launch_bounds__(128) k_set2set(
    const float* __restrict__ hfin, const int* __restrict__ batch,
    const float* __restrict__ w_ih, const float* __restrict__ w_hh,
    const float* __restrict__ b_ih, const float* __restrict__ b_hh,
    const float* __restrict__ l1w, const float* __restrict__ l1b,
    float* __restrict__ outp)
{
    const int b = blockIdx.x;
    const int tid = threadIdx.x, warp = tid >> 5, lane = tid & 31;
    __shared__ float s_qstar[128], s_g[256], s_q[64], s_cl[64], s_rvec[64];
    __shared__ float s_wmax[4], s_wsum[4];
    __shared__ float s_gmax, s_gsum;
    __shared__ int s_s, s_e;

    if (tid == 0) {
        int lo = 0, hi = cN;
        while (lo < hi) { int mid = (lo + hi) >> 1; if (batch[mid] < b) lo = mid + 1; else hi = mid; }
        s_s = lo;
        hi = cN;
        while (lo < hi) { int mid = (lo + hi) >> 1; if (batch[mid] < b + 1) lo = mid + 1; else hi = mid; }
        s_e = lo;
    }
    s_qstar[tid] = 0.0f;
    if (tid < 64) { s_q[tid] = 0.0f; s_cl[tid] = 0.0f; }
    __syncthreads();

    for (int t = 0; t < 3; t++) {
        float g0 = b_ih[tid] + b_hh[tid];
        float g1 = b_ih[tid + 128] + b_hh[tid + 128];
#pragma unroll 4
        for (int k = 0; k < 128; k++) {
            float qv = s_qstar[k];
            g0 += qv * w_ih[k * 256 + tid];
            g1 += qv * w_ih[k * 256 + tid + 128];
        }
#pragma unroll 4
        for (int k = 0; k < 64; k++) {
            float hv = s_q[k];
            g0 += hv * w_hh[k * 256 + tid];
            g1 += hv * w_hh[k * 256 + tid + 128];
        }
        s_g[tid] = g0; s_g[tid + 128] = g1;
        __syncthreads();
        if (tid < 64) {
            float ig = sigm(s_g[tid]), fg = sigm(s_g[64 + tid]);
            float gg = tanhf(s_g[128 + tid]), og = sigm(s_g[192 + tid]);
            float c = fg * s_cl[tid] + ig * gg;
            s_cl[tid] = c;
            s_q[tid] = og * tanhf(c);
            s_rvec[tid] = 0.0f;
        }
        __syncthreads();

        const int ns = s_s, ne = s_e;
        float wmax = -1e30f;
        for (int n = ns + warp; n < ne; n += 4) {
            const float* o = hfin + (size_t)n * cD;
            float d = o[lane] * s_q[lane] + o[32 + lane] * s_q[32 + lane];
#pragma unroll
            for (int off = 16; off; off >>= 1) d += __shfl_xor_sync(0xffffffffu, d, off);
            wmax = fmaxf(wmax, d);
        }
        if (lane == 0) s_wmax[warp] = wmax;
        __syncthreads();
        if (tid == 0)
            s_gmax = fmaxf(fmaxf(s_wmax[0], s_wmax[1]), fmaxf(s_wmax[2], s_wmax[3]));
        __syncthreads();
        const float gmax = s_gmax;

        float wsum = 0.0f, rv0 = 0.0f, rv1 = 0.0f;
        for (int n = ns + warp; n < ne; n += 4) {
            const float* o = hfin + (size_t)n * cD;
            float d = o[lane] * s_q[lane] + o[32 + lane] * s_q[32 + lane];
#pragma unroll
            for (int off = 16; off; off >>= 1) d += __shfl_xor_sync(0xffffffffu, d, off);
            float ee = expf(d - gmax);
            wsum += ee;
            rv0 += ee * o[lane];
            rv1 += ee * o[32 + lane];
        }
        if (lane == 0) s_wsum[warp] = wsum;
        atomicAdd(&s_rvec[lane], rv0);
        atomicAdd(&s_rvec[32 + lane], rv1);
        __syncthreads();
        if (tid == 0) s_gsum = s_wsum[0] + s_wsum[1] + s_wsum[2] + s_wsum[3];
        __syncthreads();

        if (tid < 64) s_qstar[tid] = s_q[tid];
        else {
            float denom = s_gsum;
            s_qstar[tid] = (denom > 0.0f) ? s_rvec[tid - 64] / denom : 0.0f;
        }
        __syncthreads();
    }

    if (tid < 64) {
        float acc = l1b[tid];
#pragma unroll 4
        for (int k = 0; k < 128; k++) acc += s_qstar[k] * l1w[k * cD + tid];
        outp[b * cD + tid] = fmaxf(acc, 0.0f);
    }
}

// ---------------- launch ----------------
extern "C" void kernel_launch(void* const* d_in, const int* in_sizes, int n_in,
                              void* d_out, int out_size) {
    const float* x        = (const float*)d_in[0];
    const float* ea       = (const float*)d_in[1];
    const int*   ei       = (const int*)d_in[2];
    const int*   batch    = (const int*)d_in[3];
    const float* lin0_w   = (const float*)d_in[4];
    const float* lin0_b   = (const float*)d_in[5];
    const float* net_w1   = (const float*)d_in[6];
    const float* net_b1   = (const float*)d_in[7];
    const float* net_w2   = (const float*)d_in[8];
    const float* net_b2   = (const float*)d_in[9];
    const float* conv_root= (const float*)d_in[10];
    const float* conv_bias= (const float*)d_in[11];
    const float* gru_w_ih = (const float*)d_in[12];
    const float* gru_w_hh = (const float*)d_in[13];
    const float* gru_b_ih = (const float*)d_in[14];
    const float* gru_b_hh = (const float*)d_in[15];
    const float* lstm_w_ih= (const float*)d_in[16];
    const float* lstm_w_hh= (const float*)d_in[17];
    const float* lstm_b_ih= (const float*)d_in[18];
    const float* lstm_b_hh= (const float*)d_in[19];
    const float* lin1_w   = (const float*)d_in[20];
    const float* lin1_b   = (const float*)d_in[21];
    float* out = (float*)d_out;

    const int* src = ei;
    const int* dst = ei + cE;

    void* p;
    cudaGetSymbolAddress(&p, g_h0);     float* p_h0 = (float*)p;
    cudaGetSymbolAddress(&p, g_h1);     float* p_h1 = (float*)p;
    cudaGetSymbolAddress(&p, g_hreluh); __half* p_hrh = (__half*)p;
    cudaGetSymbolAddress(&p, g_w2T);    __half* p_w2T = (__half*)p;
    cudaGetSymbolAddress(&p, g_ewh);    __half* p_ewh = (__half*)p;
    cudaGetSymbolAddress(&p, g_agg);    float* p_agg = (float*)p;
    cudaGetSymbolAddress(&p, g_CG);     float* p_CG = (float*)p;
    cudaGetSymbolAddress(&p, g_G1);     float* p_G1 = (float*)p;
    cudaGetSymbolAddress(&p, g_Wcat);   float* p_Wcat = (float*)p;
    cudaGetSymbolAddress(&p, g_bcat);   float* p_bcat = (float*)p;
    cudaGetSymbolAddress(&p, g_deg);    float* p_deg = (float*)p;

    const int T = 256;
    cudaFuncSetAttribute(k_ewgemm, cudaFuncAttributeMaxDynamicSharedMemorySize, EW_SMEM);
    cudaFuncSetAttribute(k_nodegemm, cudaFuncAttributeMaxDynamicSharedMemorySize, NG_SMEM);
    cudaFuncSetAttribute(k_mgemm, cudaFuncAttributeMaxDynamicSharedMemorySize, NG_SMEM);

    // fused init: edge1 | lin0+aggzero | prepB | prepW | deg_zero
    k_init<<<UB_TOTAL, 256>>>(ea, net_w1, net_b1, p_hrh,
                              x, lin0_w, lin0_b, p_h0, p_agg,
                              net_w2, p_w2T,
                              conv_root, gru_w_hh, gru_b_hh, p_Wcat, p_bcat,
                              p_deg);
    k_deg<<<(cE + T - 1) / T, T>>>(dst, p_deg);

    {
        dim3 grid(cDSQ / 128, (cE + 127) / 128);   // 32 x 313
        k_ewgemm<<<grid, 256, EW_SMEM>>>(p_hrh, p_w2T, net_b2, p_ewh);
    }

    // 3 message-passing steps
    for (int s = 0; s < 3; s++) {
        float* cur = (s & 1) ? p_h1 : p_h0;
        float* nxt = (s & 1) ? p_h0 : p_h1;

        {
            dim3 blk(32, 8);
            k_msg<<<(cE * 2 + 7) / 8, blk>>>(cur, p_ewh, src, dst, p_agg);
        }
        {
            dim3 grid(4, (cN + 127) / 128);
            k_nodegemm<<<grid, 128, NG_SMEM>>>(cN, 4 * cD, cur, p_Wcat, p_bcat, p_CG, 4 * cD);
        }
        {
            dim3 grid(3, (cN + 127) / 128);
            k_mgemm<<<grid, 128, NG_SMEM>>>(cN, 3 * cD, p_agg, p_CG, p_deg, conv_bias,
                                            gru_w_ih, gru_b_ih, p_G1, 3 * cD);
        }
        k_gate<<<(cN * cD + T - 1) / T, T>>>(p_G1, p_CG, cur, nxt, p_agg);
    }
    float* p_hfin = p_h1;

    // fused Set2Set (3 iterations) + lin1
    k_set2set<<<cB, 128>>>(p_hfin, batch, lstm_w_ih, lstm_w_hh, lstm_b_ih, lstm_b_hh,
                           lin1_w, lin1_b, out);
}